// round 15
// baseline (speedup 1.0000x reference)
#include <cuda_runtime.h>
#include <cuda_bf16.h>
#include <math.h>
#include <stdint.h>

// Problem constants (fixed by setup_inputs)
#define NB      8
#define NA      16
#define NL      80
#define DIM     128
#define NH      6
#define HD      768
#define N_AGT   128
#define N_NODE  768
#define SPS     96
#define NQKV    2304          // 3 * HD
#define LN_EPS  1e-5f

// Scratch (device globals: no allocations allowed)
__device__ __nv_bfloat16 g_Nhi[N_NODE * DIM];     // nodes hi  [768][128]
__device__ __nv_bfloat16 g_Nlo[N_NODE * DIM];     // nodes lo
__device__ __nv_bfloat16 g_Whi[DIM * NQKV];       // weights hi [128][2304]
__device__ __nv_bfloat16 g_Wlo[DIM * NQKV];       // weights lo
__device__ float g_QKV[N_NODE * NQKV];            // cols: [Q | K | V(relu)]
__device__ float g_part[NH * N_AGT * DIM];        // per-head attO@Wout1 partials

// ---------------------------------------------------------------------------
// Helpers (mma.sync / ldmatrix — valid on compute_103)
// ---------------------------------------------------------------------------
__device__ __forceinline__ uint32_t smem_u32(const void* p) {
    uint32_t a;
    asm("{ .reg .u64 t; cvta.to.shared.u64 t, %1; cvt.u32.u64 %0, t; }"
        : "=r"(a) : "l"(p));
    return a;
}
__device__ __forceinline__ void ldsm4(uint32_t* r, uint32_t a) {
    asm volatile("ldmatrix.sync.aligned.m8n8.x4.shared.b16 {%0,%1,%2,%3}, [%4];"
                 : "=r"(r[0]), "=r"(r[1]), "=r"(r[2]), "=r"(r[3]) : "r"(a));
}
__device__ __forceinline__ void ldsm2t(uint32_t* r, uint32_t a) {
    asm volatile("ldmatrix.sync.aligned.m8n8.x2.trans.shared.b16 {%0,%1}, [%2];"
                 : "=r"(r[0]), "=r"(r[1]) : "r"(a));
}
__device__ __forceinline__ void mma_bf16(float* d, const uint32_t* a,
                                         const uint32_t* b) {
    asm volatile(
        "mma.sync.aligned.m16n8k16.row.col.f32.bf16.bf16.f32 "
        "{%0,%1,%2,%3}, {%4,%5,%6,%7}, {%8,%9}, {%0,%1,%2,%3};"
        : "+f"(d[0]), "+f"(d[1]), "+f"(d[2]), "+f"(d[3])
        : "r"(a[0]), "r"(a[1]), "r"(a[2]), "r"(a[3]), "r"(b[0]), "r"(b[1]));
}
// bf16 hi/lo split of two floats (hi = truncate, lo = rn residual; verified r12)
__device__ __forceinline__ void split2(float x, float y,
                                       uint32_t& hi, uint32_t& lo) {
    uint32_t xb = __float_as_uint(x), yb = __float_as_uint(y);
    uint32_t h;
    asm("prmt.b32 %0, %1, %2, 0x7632;" : "=r"(h) : "r"(xb), "r"(yb));
    float xh = __uint_as_float(xb & 0xFFFF0000u);
    float yh = __uint_as_float(yb & 0xFFFF0000u);
    uint32_t l;
    asm("cvt.rn.bf16x2.f32 %0, %1, %2;" : "=r"(l) : "f"(y - yh), "f"(x - xh));
    hi = h;
    lo = l;
}

// ---------------------------------------------------------------------------
// Kernel 0: one-shot conversion. 96 CTAs x 256 threads, 4 float4 each.
// idx < 24576  -> nodes float4 (768*128/4)
// idx >= 24576 -> weights float4 (128*2304/4), combined [k][2304] layout
// ---------------------------------------------------------------------------
__global__ __launch_bounds__(256)
void prep_kernel(const float* __restrict__ agents,
                 const float* __restrict__ lanes,
                 const float* __restrict__ Wq,
                 const float* __restrict__ Wk,
                 const float* __restrict__ Wv)
{
    const int tid = threadIdx.x;
    #pragma unroll
    for (int i = 0; i < 4; ++i) {
        int idx = blockIdx.x * 1024 + i * 256 + tid;
        uint32_t h0, l0, h1, l1;
        if (idx < 24576) {
            int e4 = idx * 4;                         // element index
            const float* src = (e4 < N_AGT * DIM) ? agents + e4
                                                  : lanes + (e4 - N_AGT * DIM);
            float4 v = *(const float4*)src;
            split2(v.x, v.y, h0, l0);
            split2(v.z, v.w, h1, l1);
            *(uint2*)(g_Nhi + e4) = make_uint2(h0, h1);
            *(uint2*)(g_Nlo + e4) = make_uint2(l0, l1);
        } else {
            int widx = idx - 24576;                   // 0..73727
            int k = widx / 576;                       // 0..127
            int n4 = (widx % 576) * 4;                // 0..2300
            const float* W;
            int nl;
            if (n4 < HD)          { W = Wq; nl = n4; }
            else if (n4 < 2 * HD) { W = Wk; nl = n4 - HD; }
            else                  { W = Wv; nl = n4 - 2 * HD; }
            float4 v = *(const float4*)(W + (size_t)k * HD + nl);
            split2(v.x, v.y, h0, l0);
            split2(v.z, v.w, h1, l1);
            *(uint2*)(g_Whi + (size_t)k * NQKV + n4) = make_uint2(h0, h1);
            *(uint2*)(g_Wlo + (size_t)k * NQKV + n4) = make_uint2(l0, l1);
        }
    }
}

// ---------------------------------------------------------------------------
// Kernel 1: QKV bf16x3 MMA — 64x64 tiles, 312 CTAs x 256 threads, 70KB smem,
// copy-only fill (conversion hoisted to prep).
// ---------------------------------------------------------------------------
#define ASTR    136                      // A row stride in bf16 (272 B)
#define BSTRB   144                      // B row stride in BYTES (72 bf16)
#define OFF_AHI 0
#define OFF_ALO 17408                    // 64*272
#define OFF_BHI 34816
#define OFF_BLO 53248                    // 34816 + 128*144
#define QKV_SMEM 71680

__global__ __launch_bounds__(256)
void qkv_mma()
{
    extern __shared__ char smem[];
    const uint32_t sb = smem_u32(smem);
    const int tid = threadIdx.x, wid = tid >> 5, lane = tid & 31;
    const int t = blockIdx.x;

    int row0, col0;
    if (t < 288) { row0 = (t % 12) * 64; col0 = 768 + (t / 12) * 64; }
    else         { int tq = t - 288; row0 = (tq & 1) * 64; col0 = (tq >> 1) * 64; }

    // ---- Fill A (64 rows x 128 k): 1024 uint4 per buffer, pure copies ----
    {
        const uint4* nhi = (const uint4*)(g_Nhi + (size_t)row0 * DIM);
        const uint4* nlo = (const uint4*)(g_Nlo + (size_t)row0 * DIM);
        #pragma unroll
        for (int i = 0; i < 4; ++i) {
            int lin = tid + i * 256;         // 0..1023
            int r = lin >> 4, u = lin & 15;  // row, uint4-within-row (128bf16=16u4)
            *(uint4*)(smem + OFF_AHI + r * (ASTR * 2) + u * 16) = nhi[lin];
            *(uint4*)(smem + OFF_ALO + r * (ASTR * 2) + u * 16) = nlo[lin];
        }
    }
    // ---- Fill B (128 k x 64 n): 1024 uint4 per buffer ----
    {
        #pragma unroll
        for (int i = 0; i < 4; ++i) {
            int lin = tid + i * 256;         // 0..1023
            int k = lin >> 3, u = lin & 7;   // k row, uint4 (64bf16 = 8 u4)
            const uint4* whi = (const uint4*)(g_Whi + (size_t)k * NQKV + col0);
            const uint4* wlo = (const uint4*)(g_Wlo + (size_t)k * NQKV + col0);
            *(uint4*)(smem + OFF_BHI + k * BSTRB + u * 16) = whi[u];
            *(uint4*)(smem + OFF_BLO + k * BSTRB + u * 16) = wlo[u];
        }
    }
    __syncthreads();

    // 8 warps: 4m x 2n over 64x64 -> warp tile 16x32
    const int wm = wid >> 1, wn = wid & 1;
    const int m0 = wm * 16, n0 = wn * 32;
    float acc[4][4] = {};

    const uint32_t a_off = (uint32_t)((m0 + (lane & 15)) * ASTR + (lane >> 4) * 8) * 2;
    const uint32_t b_off = (uint32_t)((lane & 15) * BSTRB + n0 * 2);
    const uint32_t sA_hi = sb + OFF_AHI + a_off;
    const uint32_t sA_lo = sb + OFF_ALO + a_off;
    const uint32_t sB_hi = sb + OFF_BHI + b_off;
    const uint32_t sB_lo = sb + OFF_BLO + b_off;

    #pragma unroll 2
    for (int ks = 0; ks < 8; ++ks) {
        const uint32_t kbA = (uint32_t)(ks * 32);            // k along A cols
        const uint32_t kbB = (uint32_t)(ks * 16 * BSTRB);    // k along B rows
        uint32_t ah[4], al[4], bh[4][2], bl[4][2];
        ldsm4(ah, sA_hi + kbA);
        ldsm4(al, sA_lo + kbA);
        #pragma unroll
        for (int nt = 0; nt < 4; ++nt) {
            ldsm2t(bh[nt], sB_hi + kbB + nt * 16);
            ldsm2t(bl[nt], sB_lo + kbB + nt * 16);
        }
        #pragma unroll
        for (int nt = 0; nt < 4; ++nt) {
            mma_bf16(acc[nt], ah, bh[nt]);
            mma_bf16(acc[nt], ah, bl[nt]);
            mma_bf16(acc[nt], al, bh[nt]);
        }
    }

    const bool dorelu = (col0 >= 2 * HD);
    const int rbase = row0 + m0 + (lane >> 2);
    const int cbase = col0 + n0 + (lane & 3) * 2;
    #pragma unroll
    for (int nt = 0; nt < 4; ++nt) {
        float2 v01 = make_float2(acc[nt][0], acc[nt][1]);
        float2 v23 = make_float2(acc[nt][2], acc[nt][3]);
        if (dorelu) {
            v01.x = fmaxf(v01.x, 0.f); v01.y = fmaxf(v01.y, 0.f);
            v23.x = fmaxf(v23.x, 0.f); v23.y = fmaxf(v23.y, 0.f);
        }
        int c = cbase + nt * 8;
        *(float2*)(g_QKV + (size_t)rbase * NQKV + c) = v01;
        *(float2*)(g_QKV + (size_t)(rbase + 8) * NQKV + c) = v23;
    }
}

// ---------------------------------------------------------------------------
// Kernel 2: attention + per-head Wout1 partial. 48 CTAs x 512 threads.
// (verified rounds 10-14)
// ---------------------------------------------------------------------------
#define KP 132
#define SP 100
#define ATTN_SMEM ((SPS*KP + SPS*DIM + NA*KP + NA*SP) * 4)

__global__ __launch_bounds__(512)
void attn_kernel(const float* __restrict__ Wout1)
{
    const int cta = blockIdx.x;
    const int b = cta / NH;
    const int h = cta % NH;
    const int tid = threadIdx.x, wid = tid >> 5, lane = tid & 31;
    extern __shared__ float sm[];
    float* Kt = sm;                      // [96][KP]
    float* Vt = Kt + SPS * KP;           // [96][128]
    float* Qs = Vt + SPS * DIM;          // [16][KP] -> later Ot[16][128]
    float* S  = Qs + NA * KP;            // [16][SP]

    #pragma unroll
    for (int i = 0; i < 6; ++i) {
        int lin = tid + i * 512;         // 0..3071
        int j = lin >> 5, f = lin & 31;
        int g = (j < NA) ? (b * NA + j) : (N_AGT + b * NL + (j - NA));
        const float* base = g_QKV + (size_t)g * NQKV + h * DIM + f * 4;
        *(float4*)(Kt + j * KP + f * 4) = *(const float4*)(base + HD);
        *(float4*)(Vt + j * DIM + f * 4) = *(const float4*)(base + 2 * HD);
    }
    {
        int r = tid >> 5, f = tid & 31;  // 512 = 16 rows x 32 float4
        *(float4*)(Qs + r * KP + f * 4) =
            *(const float4*)(g_QKV + (size_t)(b * NA + r) * NQKV + h * DIM + f * 4);
    }
    __syncthreads();

    // Scores: 384 threads, thread = (4 rows, 1 col)
    const float scale = 0.08838834764831845f;
    if (tid < 384) {
        const int ti = tid / SPS;        // 0..3
        const int tj = tid % SPS;        // col j
        const int ib = ti * 4;
        float acc[4] = {};
        #pragma unroll 4
        for (int k = 0; k < DIM; k += 4) {
            float4 kv = *(const float4*)(Kt + tj * KP + k);
            #pragma unroll
            for (int r = 0; r < 4; ++r) {
                float4 q = *(const float4*)(Qs + (ib + r) * KP + k);
                acc[r] += q.x * kv.x + q.y * kv.y + q.z * kv.z + q.w * kv.w;
            }
        }
        #pragma unroll
        for (int r = 0; r < 4; ++r)
            S[(ib + r) * SP + tj] = acc[r] * scale;
    }
    __syncthreads();

    // Softmax: warp w -> row w
    {
        const int i = wid;
        float v0 = S[i * SP + lane];
        float v1 = S[i * SP + lane + 32];
        float v2 = S[i * SP + lane + 64];
        float m = fmaxf(fmaxf(v0, v1), v2);
        #pragma unroll
        for (int off = 16; off > 0; off >>= 1)
            m = fmaxf(m, __shfl_xor_sync(0xffffffffu, m, off));
        float e0 = __expf(v0 - m), e1 = __expf(v1 - m), e2 = __expf(v2 - m);
        float s = e0 + e1 + e2;
        #pragma unroll
        for (int off = 16; off > 0; off >>= 1)
            s += __shfl_xor_sync(0xffffffffu, s, off);
        float rinv = 1.0f / s;
        S[i * SP + lane]      = e0 * rinv;
        S[i * SP + lane + 32] = e1 * rinv;
        S[i * SP + lane + 64] = e2 * rinv;
    }
    __syncthreads();

    // PV: warp = row, lane = 4 cols
    float* Ot = Qs;
    {
        const int i = wid;
        const int d = lane * 4;
        float4 a0 = make_float4(0.f, 0.f, 0.f, 0.f);
        #pragma unroll 4
        for (int k = 0; k < SPS; ++k) {
            float p = S[i * SP + k];
            float4 v = *(const float4*)(Vt + k * DIM + d);
            a0.x += p * v.x; a0.y += p * v.y; a0.z += p * v.z; a0.w += p * v.w;
        }
        *(float4*)(Ot + i * DIM + d) = a0;
    }
    __syncthreads();

    // Partial P1 = Ot(16x128) @ Wout1[h*128 .. +128, :]  (4-way k split)
    {
        const int c = tid & 127;
        const int ks = tid >> 7;         // 0..3
        float acc[NA] = {};
        const float* Wb = Wout1 + (size_t)(h * DIM + ks * 32) * DIM + c;
        #pragma unroll 8
        for (int kk = 0; kk < 32; ++kk) {
            float w = Wb[kk * DIM];
            const float* o = Ot + ks * 32 + kk;
            #pragma unroll
            for (int r = 0; r < NA; ++r)
                acc[r] += o[r * DIM] * w;
        }
        float* red = Kt;                 // [3][16][128] fits in Kt region
        if (ks > 0) {
            #pragma unroll
            for (int r = 0; r < NA; ++r)
                red[(ks - 1) * (NA * DIM) + r * DIM + c] = acc[r];
        }
        __syncthreads();
        if (ks == 0) {
            float* dst = g_part + (size_t)h * N_AGT * DIM +
                         (size_t)(b * NA) * DIM + c;
            #pragma unroll
            for (int r = 0; r < NA; ++r)
                dst[r * DIM] = acc[r] + red[r * DIM + c]
                                      + red[NA * DIM + r * DIM + c]
                                      + red[2 * NA * DIM + r * DIM + c];
        }
    }
}

// ---------------------------------------------------------------------------
// Kernel 3: fused tail — 1 agent row per block, 512 threads (verified r7-14)
// ---------------------------------------------------------------------------
__global__ __launch_bounds__(512)
void tail_kernel(const float* __restrict__ agents,
                 const float* __restrict__ Wout2,
                 const float* __restrict__ W1,
                 const float* __restrict__ lng,
                 const float* __restrict__ lnb,
                 const float* __restrict__ W2,
                 float* __restrict__ out)
{
    const int r = blockIdx.x;
    const int tid = threadIdx.x;
    const int c = tid & 127;
    const int ks = tid >> 7;              // 0..3

    __shared__ float s_ar[DIM];
    __shared__ float s_t1[DIM];
    __shared__ float s_h[DIM];
    __shared__ float s_p[4][DIM];
    __shared__ float s_red[8];

    float wv2[32], wv1[32];
    {
        const float* w2b = Wout2 + (size_t)(ks * 32) * DIM + c;
        const float* w1b = W1 + (size_t)(ks * 32) * DIM + c;
        #pragma unroll
        for (int k = 0; k < 32; ++k) {
            wv2[k] = w2b[k * DIM];
            wv1[k] = w1b[k * DIM];
        }
    }
    float tp = 0.0f;
    if (ks < 3) {
        const float* gp = g_part + (size_t)(2 * ks) * N_AGT * DIM + (size_t)r * DIM + c;
        tp = gp[0] + gp[N_AGT * DIM];
    }
    const float ar = agents[r * DIM + c];
    const float g_c = lng[c], b_c = lnb[c];

    s_p[ks][c] = tp;
    __syncthreads();
    if (ks == 0) {
        s_t1[c] = fmaxf(s_p[0][c] + s_p[1][c] + s_p[2][c], 0.0f);
        s_ar[c] = ar;
    }
    __syncthreads();

    float pp = 0.0f;
    {
        const float* t1b = s_t1 + ks * 32;
        const float* arb = s_ar + ks * 32;
        #pragma unroll
        for (int k = 0; k < 32; ++k)
            pp += t1b[k] * wv2[k] + arb[k] * wv1[k];
    }
    s_p[ks][c] = pp;

    float wv3[32];
    {
        const float* w3b = W2 + (size_t)(ks * 32) * DIM + c;
        #pragma unroll
        for (int k = 0; k < 32; ++k) wv3[k] = w3b[k * DIM];
    }
    __syncthreads();

    const float pre = s_p[0][c] + s_p[1][c] + s_p[2][c] + s_p[3][c];

    if (ks == 0) {
        float s1 = pre, s2 = pre * pre;
        #pragma unroll
        for (int off = 16; off > 0; off >>= 1) {
            s1 += __shfl_xor_sync(0xffffffffu, s1, off);
            s2 += __shfl_xor_sync(0xffffffffu, s2, off);
        }
        if ((c & 31) == 0) {
            s_red[c >> 5] = s1;
            s_red[4 + (c >> 5)] = s2;
        }
    }
    __syncthreads();

    if (ks == 0) {
        float mu = (s_red[0] + s_red[1] + s_red[2] + s_red[3]) * (1.0f / 128.0f);
        float ex2 = (s_red[4] + s_red[5] + s_red[6] + s_red[7]) * (1.0f / 128.0f);
        float var = ex2 - mu * mu;
        float hn = (pre - mu) * rsqrtf(var + LN_EPS) * g_c + b_c;
        s_h[c] = fmaxf(hn, 0.0f);
    }
    __syncthreads();

    float op = 0.0f;
    {
        const float* hb = s_h + ks * 32;
        #pragma unroll
        for (int k = 0; k < 32; ++k) op += hb[k] * wv3[k];
    }
    s_p[ks][c] = op;
    __syncthreads();
    if (ks == 0) {
        float v = s_p[0][c] + s_p[1][c] + s_p[2][c] + s_p[3][c] + ar;
        out[r * DIM + c] = fmaxf(v, 0.0f);
    }
}

// ---------------------------------------------------------------------------
extern "C" void kernel_launch(void* const* d_in, const int* in_sizes, int n_in,
                              void* d_out, int out_size)
{
    const float* agents = (const float*)d_in[0];
    const float* lanes  = (const float*)d_in[1];
    const float* Wq     = (const float*)d_in[2];
    const float* Wk     = (const float*)d_in[3];
    const float* Wv     = (const float*)d_in[4];
    const float* Wout1  = (const float*)d_in[5];
    const float* Wout2  = (const float*)d_in[6];
    const float* W1     = (const float*)d_in[7];
    const float* lng    = (const float*)d_in[8];
    const float* lnb    = (const float*)d_in[9];
    const float* W2     = (const float*)d_in[10];
    (void)in_sizes; (void)n_in; (void)out_size;

    cudaFuncSetAttribute(qkv_mma,
                         cudaFuncAttributeMaxDynamicSharedMemorySize, QKV_SMEM);
    cudaFuncSetAttribute(attn_kernel,
                         cudaFuncAttributeMaxDynamicSharedMemorySize, ATTN_SMEM);

    prep_kernel<<<96, 256>>>(agents, lanes, Wq, Wk, Wv);
    qkv_mma<<<312, 256, QKV_SMEM>>>();
    attn_kernel<<<NB * NH, 512, ATTN_SMEM>>>(Wout1);
    tail_kernel<<<N_AGT, 512>>>(agents, Wout2, W1, lng, lnb, W2,
                                (float*)d_out);
}

// round 17
// speedup vs baseline: 1.2572x; 1.2572x over previous
#include <cuda_runtime.h>
#include <cuda_bf16.h>
#include <math.h>
#include <stdint.h>

// Problem constants (fixed by setup_inputs)
#define NB      8
#define NA      16
#define NL      80
#define DIM     128
#define NH      6
#define HD      768
#define N_AGT   128
#define N_NODE  768
#define SPS     96
#define NQKV    2304          // 3 * HD
#define LN_EPS  1e-5f

// Scratch (device globals: no allocations allowed)
__device__ __nv_bfloat16 g_QKVhi[N_NODE * NQKV];  // [768][2304] bf16 hi
__device__ __nv_bfloat16 g_QKVlo[N_NODE * NQKV];  // lo
__device__ __nv_bfloat16 g_W1hi_full[HD * DIM];   // Wout1 [768][128] bf16 hi
__device__ __nv_bfloat16 g_W1lo_full[HD * DIM];   // lo
__device__ float g_part[NH * N_AGT * DIM];        // per-head attO@Wout1 partials

// ---------------------------------------------------------------------------
// Helpers (mma.sync / ldmatrix — valid on compute_103)
// ---------------------------------------------------------------------------
__device__ __forceinline__ uint32_t smem_u32(const void* p) {
    uint32_t a;
    asm("{ .reg .u64 t; cvta.to.shared.u64 t, %1; cvt.u32.u64 %0, t; }"
        : "=r"(a) : "l"(p));
    return a;
}
__device__ __forceinline__ void ldsm4(uint32_t* r, uint32_t a) {
    asm volatile("ldmatrix.sync.aligned.m8n8.x4.shared.b16 {%0,%1,%2,%3}, [%4];"
                 : "=r"(r[0]), "=r"(r[1]), "=r"(r[2]), "=r"(r[3]) : "r"(a));
}
__device__ __forceinline__ void ldsm2(uint32_t* r, uint32_t a) {
    asm volatile("ldmatrix.sync.aligned.m8n8.x2.shared.b16 {%0,%1}, [%2];"
                 : "=r"(r[0]), "=r"(r[1]) : "r"(a));
}
__device__ __forceinline__ void ldsm2t(uint32_t* r, uint32_t a) {
    asm volatile("ldmatrix.sync.aligned.m8n8.x2.trans.shared.b16 {%0,%1}, [%2];"
                 : "=r"(r[0]), "=r"(r[1]) : "r"(a));
}
__device__ __forceinline__ void mma_bf16(float* d, const uint32_t* a,
                                         const uint32_t* b) {
    asm volatile(
        "mma.sync.aligned.m16n8k16.row.col.f32.bf16.bf16.f32 "
        "{%0,%1,%2,%3}, {%4,%5,%6,%7}, {%8,%9}, {%0,%1,%2,%3};"
        : "+f"(d[0]), "+f"(d[1]), "+f"(d[2]), "+f"(d[3])
        : "r"(a[0]), "r"(a[1]), "r"(a[2]), "r"(a[3]), "r"(b[0]), "r"(b[1]));
}
// bf16 hi/lo split of two floats (hi = truncate, lo = rn residual; verified r12)
__device__ __forceinline__ void split2(float x, float y,
                                       uint32_t& hi, uint32_t& lo) {
    uint32_t xb = __float_as_uint(x), yb = __float_as_uint(y);
    uint32_t h;
    asm("prmt.b32 %0, %1, %2, 0x7632;" : "=r"(h) : "r"(xb), "r"(yb));
    float xh = __uint_as_float(xb & 0xFFFF0000u);
    float yh = __uint_as_float(yb & 0xFFFF0000u);
    uint32_t l;
    asm("cvt.rn.bf16x2.f32 %0, %1, %2;" : "=r"(l) : "f"(y - yh), "f"(x - xh));
    hi = h;
    lo = l;
}

// ---------------------------------------------------------------------------
// Kernel 1: QKV bf16x3 MMA — 64x64 tiles, 320 CTAs x 256 threads.
// CTAs 0..311: GEMM tiles. CTAs 312..319: convert Wout1 (768x128) to bf16
// hi/lo — 3072 float4 per CTA x 8 CTAs = 24576 = full matrix (r16 bug fixed).
// Outputs stored as bf16 hi/lo pairs (MMA-ready for attn).
// ---------------------------------------------------------------------------
#define ASTR    136                      // A row stride in bf16 (272 B)
#define BSTRB   144                      // B row stride in BYTES (72 bf16)
#define OFF_AHI 0
#define OFF_ALO 17408                    // 64*272
#define OFF_BHI 34816
#define OFF_BLO 53248                    // 34816 + 128*144
#define QKV_SMEM 71680

__global__ __launch_bounds__(256)
void qkv_mma(const float* __restrict__ agents,
             const float* __restrict__ lanes,
             const float* __restrict__ Wq,
             const float* __restrict__ Wk,
             const float* __restrict__ Wv,
             const float* __restrict__ Wout1)
{
    extern __shared__ char smem[];
    const uint32_t sb = smem_u32(smem);
    const int tid = threadIdx.x, wid = tid >> 5, lane = tid & 31;
    const int t = blockIdx.x;

    if (t >= 312) {                       // Wout1 conversion: 768x128 f32
        #pragma unroll
        for (int i = 0; i < 12; ++i) {    // 12*256 = 3072 float4 per CTA
            int idx = (t - 312) * 3072 + i * 256 + tid;   // 0..24575
            int e4 = idx * 4;
            float4 v = *(const float4*)(Wout1 + e4);
            uint32_t h0, l0, h1, l1;
            split2(v.x, v.y, h0, l0);
            split2(v.z, v.w, h1, l1);
            *(uint2*)(g_W1hi_full + e4) = make_uint2(h0, h1);
            *(uint2*)(g_W1lo_full + e4) = make_uint2(l0, l1);
        }
        return;
    }

    int row0, col0;
    if (t < 288) { row0 = (t % 12) * 64; col0 = 768 + (t / 12) * 64; }
    else         { int tq = t - 288; row0 = (tq & 1) * 64; col0 = (tq >> 1) * 64; }
    const float* __restrict__ W;
    int jl0;
    if (col0 < HD)          { W = Wq; jl0 = col0; }
    else if (col0 < 2 * HD) { W = Wk; jl0 = col0 - HD; }
    else                    { W = Wv; jl0 = col0 - 2 * HD; }

    // ---- Fill A (64 rows x 128 k) ----
    #pragma unroll
    for (int i = 0; i < 8; ++i) {
        int lin = tid + i * 256;
        int q4 = (lin & 31) * 4;
        int r = lin >> 5;
        int grow = row0 + r;
        const float* src = (grow < N_AGT) ? agents + (size_t)grow * DIM
                                          : lanes + (size_t)(grow - N_AGT) * DIM;
        float4 av = *(const float4*)(src + q4);
        uint32_t h0, l0, h1, l1;
        split2(av.x, av.y, h0, l0);
        split2(av.z, av.w, h1, l1);
        *(uint2*)(smem + OFF_AHI + r * (ASTR * 2) + q4 * 2) = make_uint2(h0, h1);
        *(uint2*)(smem + OFF_ALO + r * (ASTR * 2) + q4 * 2) = make_uint2(l0, l1);
    }
    // ---- Fill B (128 k x 64 n) ----
    #pragma unroll
    for (int i = 0; i < 8; ++i) {
        int lin = tid + i * 256;
        int n4 = (lin & 15) * 4;
        int k = lin >> 4;
        float4 bv = *(const float4*)(W + (size_t)k * HD + jl0 + n4);
        uint32_t h0, l0, h1, l1;
        split2(bv.x, bv.y, h0, l0);
        split2(bv.z, bv.w, h1, l1);
        *(uint2*)(smem + OFF_BHI + k * BSTRB + n4 * 2) = make_uint2(h0, h1);
        *(uint2*)(smem + OFF_BLO + k * BSTRB + n4 * 2) = make_uint2(l0, l1);
    }
    __syncthreads();

    // 8 warps: 4m x 2n over 64x64 -> warp tile 16x32
    const int wm = wid >> 1, wn = wid & 1;
    const int m0 = wm * 16, n0 = wn * 32;
    float acc[4][4] = {};

    const uint32_t a_off = (uint32_t)((m0 + (lane & 15)) * ASTR + (lane >> 4) * 8) * 2;
    const uint32_t b_off = (uint32_t)((lane & 15) * BSTRB + n0 * 2);
    const uint32_t sA_hi = sb + OFF_AHI + a_off;
    const uint32_t sA_lo = sb + OFF_ALO + a_off;
    const uint32_t sB_hi = sb + OFF_BHI + b_off;
    const uint32_t sB_lo = sb + OFF_BLO + b_off;

    #pragma unroll 2
    for (int ks = 0; ks < 8; ++ks) {
        const uint32_t kbA = (uint32_t)(ks * 32);
        const uint32_t kbB = (uint32_t)(ks * 16 * BSTRB);
        uint32_t ah[4], al[4], bh[4][2], bl[4][2];
        ldsm4(ah, sA_hi + kbA);
        ldsm4(al, sA_lo + kbA);
        #pragma unroll
        for (int nt = 0; nt < 4; ++nt) {
            ldsm2t(bh[nt], sB_hi + kbB + nt * 16);
            ldsm2t(bl[nt], sB_lo + kbB + nt * 16);
        }
        #pragma unroll
        for (int nt = 0; nt < 4; ++nt) {
            mma_bf16(acc[nt], ah, bh[nt]);
            mma_bf16(acc[nt], ah, bl[nt]);
            mma_bf16(acc[nt], al, bh[nt]);
        }
    }

    const bool dorelu = (col0 >= 2 * HD);
    const int rbase = row0 + m0 + (lane >> 2);
    const int cbase = col0 + n0 + (lane & 3) * 2;
    #pragma unroll
    for (int nt = 0; nt < 4; ++nt) {
        float a0 = acc[nt][0], a1 = acc[nt][1], a2 = acc[nt][2], a3 = acc[nt][3];
        if (dorelu) {
            a0 = fmaxf(a0, 0.f); a1 = fmaxf(a1, 0.f);
            a2 = fmaxf(a2, 0.f); a3 = fmaxf(a3, 0.f);
        }
        uint32_t h01, l01, h23, l23;
        split2(a0, a1, h01, l01);
        split2(a2, a3, h23, l23);
        int c = cbase + nt * 8;
        size_t o0 = (size_t)rbase * NQKV + c;
        size_t o8 = (size_t)(rbase + 8) * NQKV + c;
        *(uint32_t*)(g_QKVhi + o0) = h01;
        *(uint32_t*)(g_QKVlo + o0) = l01;
        *(uint32_t*)(g_QKVhi + o8) = h23;
        *(uint32_t*)(g_QKVlo + o8) = l23;
    }
}

// ---------------------------------------------------------------------------
// Kernel 2: full tensor-core attention. 48 CTAs x 512 threads.
// scores (mma) -> softmax (f32) -> PV (mma) -> O@Wout1_h (mma) -> g_part.
// ---------------------------------------------------------------------------
#define RS       272                      // bf16 row stride in bytes
#define OFF_QHI  0                        // [16][RS]
#define OFF_QLO  4352
#define OFF_KHI  8704                     // [96][RS]
#define OFF_KLO  34816
#define OFF_VHI  60928                    // [96][RS]
#define OFF_VLO  87040
#define OFF_WHI  113152                   // [128][RS]
#define OFF_WLO  147968
#define OFF_S    182784                   // f32 [16][100]
#define SSTR     100
#define OFF_PHI  189184                   // [16][RS]
#define OFF_PLO  193536
#define OFF_OHI  197888                   // [16][RS]
#define OFF_OLO  202240
#define ATTN_SMEM 206592

__global__ __launch_bounds__(512)
void attn_kernel()
{
    extern __shared__ char smem[];
    const uint32_t sb = smem_u32(smem);
    const int tid = threadIdx.x, wid = tid >> 5, lane = tid & 31;
    const int b = blockIdx.x / NH;
    const int h = blockIdx.x % NH;

    // ---- Load K, V (96 rows), Q (16 rows), Wout1 slice (128 rows), bf16 ----
    #pragma unroll
    for (int i = 0; i < 3; ++i) {
        int lin = tid + i * 512;              // 0..1535
        int j = lin >> 4, u = lin & 15;
        int g = (j < NA) ? (b * NA + j) : (N_AGT + b * NL + (j - NA));
        size_t kb = (size_t)g * NQKV + HD + h * DIM + u * 8;
        size_t vb = (size_t)g * NQKV + 2 * HD + h * DIM + u * 8;
        *(uint4*)(smem + OFF_KHI + j * RS + u * 16) = *(const uint4*)(g_QKVhi + kb);
        *(uint4*)(smem + OFF_KLO + j * RS + u * 16) = *(const uint4*)(g_QKVlo + kb);
        *(uint4*)(smem + OFF_VHI + j * RS + u * 16) = *(const uint4*)(g_QKVhi + vb);
        *(uint4*)(smem + OFF_VLO + j * RS + u * 16) = *(const uint4*)(g_QKVlo + vb);
    }
    if (tid < 256) {
        int j = tid >> 4, u = tid & 15;
        size_t qb = (size_t)(b * NA + j) * NQKV + h * DIM + u * 8;
        *(uint4*)(smem + OFF_QHI + j * RS + u * 16) = *(const uint4*)(g_QKVhi + qb);
        *(uint4*)(smem + OFF_QLO + j * RS + u * 16) = *(const uint4*)(g_QKVlo + qb);
    }
    #pragma unroll
    for (int i = 0; i < 4; ++i) {
        int lin = tid + i * 512;              // 0..2047
        int k = lin >> 4, u = lin & 15;
        size_t wb = (size_t)(h * DIM + k) * DIM + u * 8;
        *(uint4*)(smem + OFF_WHI + k * RS + u * 16) = *(const uint4*)(g_W1hi_full + wb);
        *(uint4*)(smem + OFF_WLO + k * RS + u * 16) = *(const uint4*)(g_W1lo_full + wb);
    }
    __syncthreads();

    float* S = (float*)(smem + OFF_S);
    const float scale = 0.08838834764831845f;

    // ---- Scores: S(16x96) = Q @ K^T. Warps 0..11, one n8-tile each ----
    if (wid < 12) {
        const int n0 = wid * 8;
        float acc[4] = {};
        const uint32_t a_off = (uint32_t)((lane & 15) * RS + (lane >> 4) * 16);
        const uint32_t b_off = (uint32_t)((n0 + (lane & 7)) * RS +
                                          ((lane & 8) ? 16 : 0));
        #pragma unroll
        for (int ks = 0; ks < 8; ++ks) {
            const uint32_t kb = (uint32_t)(ks * 32);
            uint32_t ah[4], al[4], bh[2], bl[2];
            ldsm4(ah, sb + OFF_QHI + a_off + kb);
            ldsm4(al, sb + OFF_QLO + a_off + kb);
            ldsm2(bh, sb + OFF_KHI + b_off + kb);
            ldsm2(bl, sb + OFF_KLO + b_off + kb);
            mma_bf16(acc, ah, bh);
            mma_bf16(acc, ah, bl);
            mma_bf16(acc, al, bh);
        }
        const int row = lane >> 2, cc = n0 + (lane & 3) * 2;
        S[row * SSTR + cc]           = acc[0] * scale;
        S[row * SSTR + cc + 1]       = acc[1] * scale;
        S[(row + 8) * SSTR + cc]     = acc[2] * scale;
        S[(row + 8) * SSTR + cc + 1] = acc[3] * scale;
    }
    __syncthreads();

    // ---- Softmax: warp w -> row w ----
    {
        const int i = wid;
        float v0 = S[i * SSTR + lane];
        float v1 = S[i * SSTR + lane + 32];
        float v2 = S[i * SSTR + lane + 64];
        float m = fmaxf(fmaxf(v0, v1), v2);
        #pragma unroll
        for (int off = 16; off > 0; off >>= 1)
            m = fmaxf(m, __shfl_xor_sync(0xffffffffu, m, off));
        float e0 = __expf(v0 - m), e1 = __expf(v1 - m), e2 = __expf(v2 - m);
        float s = e0 + e1 + e2;
        #pragma unroll
        for (int off = 16; off > 0; off >>= 1)
            s += __shfl_xor_sync(0xffffffffu, s, off);
        float rinv = 1.0f / s;
        S[i * SSTR + lane]      = e0 * rinv;
        S[i * SSTR + lane + 32] = e1 * rinv;
        S[i * SSTR + lane + 64] = e2 * rinv;
    }
    __syncthreads();

    // ---- Convert P to bf16 hi/lo: 768 pairs ----
    for (int lin = tid; lin < 768; lin += 512) {
        int row = lin / 48, cp = (lin % 48) * 2;
        uint32_t hh, ll;
        split2(S[row * SSTR + cp], S[row * SSTR + cp + 1], hh, ll);
        *(uint32_t*)(smem + OFF_PHI + row * RS + cp * 2) = hh;
        *(uint32_t*)(smem + OFF_PLO + row * RS + cp * 2) = ll;
    }
    __syncthreads();

    // ---- PV: O(16x128) = P @ V. 16 warps, one n8-tile each ----
    {
        const int n0 = wid * 8;
        float acc[4] = {};
        const uint32_t a_off = (uint32_t)((lane & 15) * RS + (lane >> 4) * 16);
        const uint32_t b_off = (uint32_t)((lane & 15) * RS + n0 * 2);
        #pragma unroll
        for (int ks = 0; ks < 6; ++ks) {
            const uint32_t kbA = (uint32_t)(ks * 32);
            const uint32_t kbB = (uint32_t)(ks * 16 * RS);
            uint32_t ph[4], pl[4], vh[2], vl[2];
            ldsm4(ph, sb + OFF_PHI + a_off + kbA);
            ldsm4(pl, sb + OFF_PLO + a_off + kbA);
            ldsm2t(vh, sb + OFF_VHI + b_off + kbB);
            ldsm2t(vl, sb + OFF_VLO + b_off + kbB);
            mma_bf16(acc, ph, vh);
            mma_bf16(acc, ph, vl);
            mma_bf16(acc, pl, vh);
        }
        const int row = lane >> 2, cc = n0 + (lane & 3) * 2;
        uint32_t h01, l01, h23, l23;
        split2(acc[0], acc[1], h01, l01);
        split2(acc[2], acc[3], h23, l23);
        *(uint32_t*)(smem + OFF_OHI + row * RS + cc * 2) = h01;
        *(uint32_t*)(smem + OFF_OLO + row * RS + cc * 2) = l01;
        *(uint32_t*)(smem + OFF_OHI + (row + 8) * RS + cc * 2) = h23;
        *(uint32_t*)(smem + OFF_OLO + (row + 8) * RS + cc * 2) = l23;
    }
    __syncthreads();

    // ---- P1: g_part_h(16x128) = O @ Wout1_h. 16 warps, one n8-tile each ----
    {
        const int n0 = wid * 8;
        float acc[4] = {};
        const uint32_t a_off = (uint32_t)((lane & 15) * RS + (lane >> 4) * 16);
        const uint32_t b_off = (uint32_t)((lane & 15) * RS + n0 * 2);
        #pragma unroll
        for (int ks = 0; ks < 8; ++ks) {
            const uint32_t kbA = (uint32_t)(ks * 32);
            const uint32_t kbB = (uint32_t)(ks * 16 * RS);
            uint32_t oh[4], ol[4], wh[2], wl[2];
            ldsm4(oh, sb + OFF_OHI + a_off + kbA);
            ldsm4(ol, sb + OFF_OLO + a_off + kbA);
            ldsm2t(wh, sb + OFF_WHI + b_off + kbB);
            ldsm2t(wl, sb + OFF_WLO + b_off + kbB);
            mma_bf16(acc, oh, wh);
            mma_bf16(acc, oh, wl);
            mma_bf16(acc, ol, wh);
        }
        const int row = lane >> 2, cc = n0 + (lane & 3) * 2;
        float* dst = g_part + (size_t)h * N_AGT * DIM + (size_t)(b * NA) * DIM;
        *(float2*)(dst + row * DIM + cc) = make_float2(acc[0], acc[1]);
        *(float2*)(dst + (row + 8) * DIM + cc) = make_float2(acc[2], acc[3]);
    }
}

// ---------------------------------------------------------------------------
// Kernel 3: fused tail — 1 agent row per block, 512 threads (verified r7-15)
// ---------------------------------------------------------------------------
__global__ __launch_bounds__(512)
void tail_kernel(const float* __restrict__ agents,
                 const float* __restrict__ Wout2,
                 const float* __restrict__ W1,
                 const float* __restrict__ lng,
                 const float* __restrict__ lnb,
                 const float* __restrict__ W2,
                 float* __restrict__ out)
{
    const int r = blockIdx.x;
    const int tid = threadIdx.x;
    const int c = tid & 127;
    const int ks = tid >> 7;              // 0..3

    __shared__ float s_ar[DIM];
    __shared__ float s_t1[DIM];
    __shared__ float s_h[DIM];
    __shared__ float s_p[4][DIM];
    __shared__ float s_red[8];

    float wv2[32], wv1[32];
    {
        const float* w2b = Wout2 + (size_t)(ks * 32) * DIM + c;
        const float* w1b = W1 + (size_t)(ks * 32) * DIM + c;
        #pragma unroll
        for (int k = 0; k < 32; ++k) {
            wv2[k] = w2b[k * DIM];
            wv1[k] = w1b[k * DIM];
        }
    }
    float tp = 0.0f;
    if (ks < 3) {
        const float* gp = g_part + (size_t)(2 * ks) * N_AGT * DIM + (size_t)r * DIM + c;
        tp = gp[0] + gp[N_AGT * DIM];
    }
    const float ar = agents[r * DIM + c];
    const float g_c = lng[c], b_c = lnb[c];

    s_p[ks][c] = tp;
    __syncthreads();
    if (ks == 0) {
        s_t1[c] = fmaxf(s_p[0][c] + s_p[1][c] + s_p[2][c], 0.0f);
        s_ar[c] = ar;
    }
    __syncthreads();

    float pp = 0.0f;
    {
        const float* t1b = s_t1 + ks * 32;
        const float* arb = s_ar + ks * 32;
        #pragma unroll
        for (int k = 0; k < 32; ++k)
            pp += t1b[k] * wv2[k] + arb[k] * wv1[k];
    }
    s_p[ks][c] = pp;

    float wv3[32];
    {
        const float* w3b = W2 + (size_t)(ks * 32) * DIM + c;
        #pragma unroll
        for (int k = 0; k < 32; ++k) wv3[k] = w3b[k * DIM];
    }
    __syncthreads();

    const float pre = s_p[0][c] + s_p[1][c] + s_p[2][c] + s_p[3][c];

    if (ks == 0) {
        float s1 = pre, s2 = pre * pre;
        #pragma unroll
        for (int off = 16; off > 0; off >>= 1) {
            s1 += __shfl_xor_sync(0xffffffffu, s1, off);
            s2 += __shfl_xor_sync(0xffffffffu, s2, off);
        }
        if ((c & 31) == 0) {
            s_red[c >> 5] = s1;
            s_red[4 + (c >> 5)] = s2;
        }
    }
    __syncthreads();

    if (ks == 0) {
        float mu = (s_red[0] + s_red[1] + s_red[2] + s_red[3]) * (1.0f / 128.0f);
        float ex2 = (s_red[4] + s_red[5] + s_red[6] + s_red[7]) * (1.0f / 128.0f);
        float var = ex2 - mu * mu;
        float hn = (pre - mu) * rsqrtf(var + LN_EPS) * g_c + b_c;
        s_h[c] = fmaxf(hn, 0.0f);
    }
    __syncthreads();

    float op = 0.0f;
    {
        const float* hb = s_h + ks * 32;
        #pragma unroll
        for (int k = 0; k < 32; ++k) op += hb[k] * wv3[k];
    }
    s_p[ks][c] = op;
    __syncthreads();
    if (ks == 0) {
        float v = s_p[0][c] + s_p[1][c] + s_p[2][c] + s_p[3][c] + ar;
        out[r * DIM + c] = fmaxf(v, 0.0f);
    }
}

// ---------------------------------------------------------------------------
extern "C" void kernel_launch(void* const* d_in, const int* in_sizes, int n_in,
                              void* d_out, int out_size)
{
    const float* agents = (const float*)d_in[0];
    const float* lanes  = (const float*)d_in[1];
    const float* Wq     = (const float*)d_in[2];
    const float* Wk     = (const float*)d_in[3];
    const float* Wv     = (const float*)d_in[4];
    const float* Wout1  = (const float*)d_in[5];
    const float* Wout2  = (const float*)d_in[6];
    const float* W1     = (const float*)d_in[7];
    const float* lng    = (const float*)d_in[8];
    const float* lnb    = (const float*)d_in[9];
    const float* W2     = (const float*)d_in[10];
    (void)in_sizes; (void)n_in; (void)out_size;

    cudaFuncSetAttribute(qkv_mma,
                         cudaFuncAttributeMaxDynamicSharedMemorySize, QKV_SMEM);
    cudaFuncSetAttribute(attn_kernel,
                         cudaFuncAttributeMaxDynamicSharedMemorySize, ATTN_SMEM);

    qkv_mma<<<320, 256, QKV_SMEM>>>(agents, lanes, Wq, Wk, Wv, Wout1);
    attn_kernel<<<NB * NH, 512, ATTN_SMEM>>>();
    tail_kernel<<<N_AGT, 512>>>(agents, Wout2, W1, lng, lnb, W2,
                                (float*)d_out);
}